// round 8
// baseline (speedup 1.0000x reference)
#include <cuda_runtime.h>
#include <math.h>
#include <stdint.h>

#define NTOK   20
#define DVEC   256
#define KSAMP  4096
#define NSTEP  19
#define ROWN   (KSAMP*NTOK)      /* 81920 keys per step */
#define SCAN_TPB 32
#define SCAN_BLK (KSAMP/SCAN_TPB)  /* 128 blocks, 1 warp each */

__device__ float          g_S[NTOK*6];        // [i][0..2]=x.Wf+b, [3..5]=x.Wa
__device__ uint32_t       g_key[NSTEP*ROWN];  // packed sort keys
__device__ unsigned char  g_opsT[KSAMP*20];   // ops transposed: [k][t]
__device__ float          g_score[KSAMP];
__device__ unsigned char  g_legal[KSAMP];
__device__ unsigned int   g_gmax_u = 0;       // int-mapped float max (reset)
__device__ int            g_cnt = 0;          // legal count (reset)
__device__ int            g_blocks_done = 0;  // reset by last scan block

// ---------------- Threefry-2x32 (20 rounds), identical to JAX ----------------
__host__ __device__ __forceinline__ void tf_block(uint32_t k0, uint32_t k1,
                                                  uint32_t x0, uint32_t x1,
                                                  uint32_t* o0, uint32_t* o1) {
  uint32_t ks2 = k0 ^ k1 ^ 0x1BD11BDAu;
  x0 += k0; x1 += k1;
#define TF_ROT(r) { x0 += x1; x1 = (x1 << (r)) | (x1 >> (32 - (r))); x1 ^= x0; }
  TF_ROT(13) TF_ROT(15) TF_ROT(26) TF_ROT(6)
  x0 += k1;  x1 += ks2 + 1u;
  TF_ROT(17) TF_ROT(29) TF_ROT(16) TF_ROT(24)
  x0 += ks2; x1 += k0 + 2u;
  TF_ROT(13) TF_ROT(15) TF_ROT(26) TF_ROT(6)
  x0 += k0;  x1 += k1 + 3u;
  TF_ROT(17) TF_ROT(29) TF_ROT(16) TF_ROT(24)
  x0 += k1;  x1 += ks2 + 4u;
  TF_ROT(13) TF_ROT(15) TF_ROT(26) TF_ROT(6)
  x0 += ks2; x1 += k0 + 5u;
#undef TF_ROT
  *o0 = x0; *o1 = x1;
}

__device__ __forceinline__ uint32_t tf_bits32(uint32_t k0, uint32_t k1, uint32_t i) {
  uint32_t a, b;
  tf_block(k0, k1, 0u, i, &a, &b);
  return a ^ b;
}

// ---------------- warp-per-token prep (lane owns 8 dims, shuffle-only) --------
__device__ __forceinline__ void prep_token(int i, int lane,
                                           const int* __restrict__ ids,
                                           const float* __restrict__ emb,
                                           const float* __restrict__ lv,
                                           const float* __restrict__ fx,
                                           const float* __restrict__ Wf,
                                           const float* __restrict__ Wa,
                                           const float* __restrict__ bop) {
  const unsigned FULL = 0xFFFFFFFFu;
  int id = ids[i];
  const float4* er = (const float4*)(emb + (size_t)id * DVEC);
  const float4* fr = (const float4*)(fx  + (size_t)id * DVEC);
  float4 e0 = er[lane * 2], e1 = er[lane * 2 + 1];
  float4 f0 = fr[lane * 2], f1 = fr[lane * 2 + 1];
  float lvv = lv[id];

  float ev[8] = {e0.x, e0.y, e0.z, e0.w, e1.x, e1.y, e1.z, e1.w};
  float fv[8] = {f0.x, f0.y, f0.z, f0.w, f1.x, f1.y, f1.z, f1.w};

  float m = ev[0];
#pragma unroll
  for (int j = 1; j < 8; j++) m = fmaxf(m, ev[j]);
#pragma unroll
  for (int o = 16; o; o >>= 1) m = fmaxf(m, __shfl_xor_sync(FULL, m, o));

  float ex[8]; float sm = 0.0f;
#pragma unroll
  for (int j = 0; j < 8; j++) { ex[j] = expf(ev[j] - m); sm += ex[j]; }
#pragma unroll
  for (int o = 16; o; o >>= 1) sm += __shfl_xor_sync(FULL, sm, o);

  float x[8];
#pragma unroll
  for (int j = 0; j < 8; j++) x[j] = (ex[j] / sm) * lvv + fv[j];

  float p[6] = {0, 0, 0, 0, 0, 0};
#pragma unroll
  for (int j = 0; j < 8; j++) {
    int d = lane * 8 + j;
    p[0] += x[j] * Wf[d * 3 + 0];
    p[1] += x[j] * Wf[d * 3 + 1];
    p[2] += x[j] * Wf[d * 3 + 2];
    p[3] += x[j] * Wa[d * 3 + 0];
    p[4] += x[j] * Wa[d * 3 + 1];
    p[5] += x[j] * Wa[d * 3 + 2];
  }
#pragma unroll
  for (int o = 16; o; o >>= 1) {
#pragma unroll
    for (int q = 0; q < 6; q++) p[q] += __shfl_xor_sync(FULL, p[q], o);
  }
  if (lane == 0) {
#pragma unroll
    for (int q = 0; q < 6; q++)
      g_S[i * 6 + q] = p[q] + (q < 3 ? bop[q] : 0.0f);
  }
}

// ---------------- Kernel 1: keygen + ops + prep (full occupancy) --------------
// y in [0,18]: packed sort keys for step y (one per thread, linear writes).
// y == 19   : ops, stored transposed g_opsT[k][t].
// y == 0, x<3: also run prep (20 token-warps).
__global__ __launch_bounds__(256) void keygen_kernel(
    uint32_t kg0, uint32_t kg1, uint32_t kop0, uint32_t kop1,
    const int* __restrict__ ids, const float* __restrict__ emb,
    const float* __restrict__ lv, const float* __restrict__ fx,
    const float* __restrict__ Wf, const float* __restrict__ Wa,
    const float* __restrict__ bop) {
  int y = blockIdx.y;
  int tid = threadIdx.x;

  if (y == NSTEP) {                          // ops blocks
    int n = blockIdx.x * 256 + tid;
    if (n < NSTEP * KSAMP) {
      uint32_t bits = tf_bits32(kop0, kop1, (uint32_t)n);
      uint32_t op = ((bits >> 16) % 3u + (bits & 0xFFFFu) % 3u) % 3u;
      int t = n >> 12, k = n & 4095;         // n = t*4096 + k
      g_opsT[k * 20 + t] = (unsigned char)op;
    }
    return;
  }

  if (y == 0 && blockIdx.x < 3) {            // prep: 20 token-warps
    int wf = blockIdx.x * 8 + (tid >> 5);
    if (wf < NTOK)
      prep_token(wf, tid & 31, ids, emb, lv, fx, Wf, Wa, bop);
  }

  int n = blockIdx.x * 256 + tid;            // 0..81919 (= k*20 + j)
  uint32_t idx = (uint32_t)y * (uint32_t)ROWN + (uint32_t)n;
  uint32_t key = tf_bits32(kg0, kg1, idx) >> 9;   // gumbel order == bits>>9 order
  uint32_t j = (uint32_t)(n % 20);
  g_key[idx] = ((key + 1u) << 5) | (31u - j);     // packed tie-break key
}

// ---------------- Kernel 2: thread-per-sample scan + fused reduce -------------
__global__ __launch_bounds__(SCAN_TPB) void scan_kernel(float* __restrict__ out) {
  __shared__ float sS[NTOK * 6];
  const unsigned FULL = 0xFFFFFFFFu;
  int tid = threadIdx.x;
  int k = blockIdx.x * SCAN_TPB + tid;       // sample 0..4095

#pragma unroll
  for (int q = tid; q < NTOK * 6; q += SCAN_TPB) sS[q] = g_S[q];
  __syncwarp();

  // ops: 19 bytes packed at g_opsT[k*20]
  uint32_t ow[5];
  {
    const uint32_t* p = (const uint32_t*)(g_opsT + k * 20);
#pragma unroll
    for (int q = 0; q < 5; q++) ow[q] = p[q];
  }

  // double-prefetch key rows (5 x uint4 = 80B per step, L2-resident)
  uint4 buf[3][5];
#pragma unroll
  for (int q = 0; q < 5; q++) buf[0][q] = ((const uint4*)(g_key + 0 * ROWN + k * 20))[q];
#pragma unroll
  for (int q = 0; q < 5; q++) buf[1][q] = ((const uint4*)(g_key + 1 * ROWN + k * 20))[q];

  unsigned avail = 0xFFFFFu, f1 = 0u, f2 = 0u;
  // ptr[20] packed 5 bits/slot: slots 0..11 in plo, 12..19 in phi (init: ptr[j]=j)
  unsigned long long plo = 0ull, phi = 0ull;
#pragma unroll
  for (int j = 0; j < 12; j++) plo |= (unsigned long long)j << (5 * j);
#pragma unroll
  for (int j = 12; j < 20; j++) phi |= (unsigned long long)j << (5 * (j - 12));

  float score = 0.0f;
  bool legal = true;

#pragma unroll
  for (int t = 0; t < NSTEP; t++) {
    if (t + 2 < NSTEP) {
      const uint4* p = (const uint4*)(g_key + (t + 2) * ROWN + k * 20);
#pragma unroll
      for (int q = 0; q < 5; q++) buf[(t + 2) % 3][q] = p[q];
    }
    uint32_t kk[20];
#pragma unroll
    for (int q = 0; q < 5; q++) {
      uint4 wv = buf[t % 3][q];
      kk[q * 4 + 0] = wv.x; kk[q * 4 + 1] = wv.y;
      kk[q * 4 + 2] = wv.z; kk[q * 4 + 3] = wv.w;
    }

    // thread-local masked top-2 (packed keys: value order + exact tie-break)
    uint32_t u1 = 0u, u2 = 0u;
#pragma unroll
    for (int j = 0; j < 20; j++) {
      uint32_t v = ((avail >> j) & 1u) ? kk[j] : 0u;
      uint32_t mn = min(u1, v);
      u1 = max(u1, v);
      u2 = max(u2, mn);
    }
    int b1 = (int)((~u1) & 31u), b2 = (int)((~u2) & 31u);
    avail &= ~(1u << b2);

    int op = (int)((ow[t >> 2] >> ((t & 3) * 8)) & 3u);

    int s1 = 5 * b1, s2 = 5 * b2;
    int s1l = (s1 < 60) ? s1 : 0,  s1h = (s1 >= 60) ? s1 - 60 : 0;
    int s2l = (s2 < 60) ? s2 : 0,  s2h = (s2 >= 60) ? s2 - 60 : 0;
    int pf = (int)((b1 < 12 ? (plo >> s1l) : (phi >> s1h)) & 31ull);
    int pa = (int)((b2 < 12 ? (plo >> s2l) : (phi >> s2h)) & 31ull);
    score += sS[pf * 6 + op] + sS[pa * 6 + 3 + op];

    unsigned of1 = (f1 >> b1) & 1u;
    unsigned of2 = (f2 >> b1) & 1u;
    bool bad = ((op != 2) && of1) || ((op == 1) && of2);
    legal = legal && !bad;

    if (op == 2) {                           // mod: slot b1 := copy of slot b2
      if (b1 < 12) plo = (plo & ~(31ull << s1l)) | ((unsigned long long)pa << s1l);
      else         phi = (phi & ~(31ull << s1h)) | ((unsigned long long)pa << s1h);
      unsigned a1 = (f1 >> b2) & 1u, a2 = (f2 >> b2) & 1u;
      f1 = (f1 & ~(1u << b1)) | (a1 << b1);
      f2 = (f2 & ~(1u << b1)) | (a2 << b1);
    } else if (op == 0) {
      f1 |= 1u << b1;
    } else {
      f2 |= 1u << b1;
    }
  }

  g_score[k] = score;
  g_legal[k] = legal ? 1 : 0;

  // warp-local partials -> global atomics (max exact, count exact)
  float lm = legal ? score : -INFINITY;
  int lc = legal ? 1 : 0;
#pragma unroll
  for (int o = 16; o; o >>= 1) {
    lm = fmaxf(lm, __shfl_xor_sync(FULL, lm, o));
    lc += __shfl_xor_sync(FULL, lc, o);
  }
  int last = 0;
  if (tid == 0) {
    if (lc > 0) {
      int s = __float_as_int(lm);
      unsigned enc = (unsigned)s ^ (((unsigned)(s >> 31)) | 0x80000000u);
      atomicMax(&g_gmax_u, enc);
    }
    atomicAdd(&g_cnt, lc);
    __threadfence();
    last = (atomicAdd(&g_blocks_done, 1) == SCAN_BLK - 1);
  }
  last = __shfl_sync(FULL, last, 0);
  if (!last) return;
  __threadfence();                           // acquire scores/legal/max/cnt

  unsigned genc = g_gmax_u;
  int cnt = g_cnt;
  int gs = (genc & 0x80000000u) ? (int)(genc ^ 0x80000000u) : (int)(~genc);
  float gm = __int_as_float(gs);

  float sum = 0.0f;
  int q0 = tid * (KSAMP / SCAN_TPB);         // contiguous 128-sample chunk
#pragma unroll 8
  for (int q = 0; q < KSAMP / SCAN_TPB; q += 4) {
    float4 sc = *(const float4*)(g_score + q0 + q);
    uchar4 lg = *(const uchar4*)(g_legal + q0 + q);
    if (lg.x) sum += __expf(sc.x - gm);
    if (lg.y) sum += __expf(sc.y - gm);
    if (lg.z) sum += __expf(sc.z - gm);
    if (lg.w) sum += __expf(sc.w - gm);
  }
#pragma unroll
  for (int o = 16; o; o >>= 1) sum += __shfl_xor_sync(FULL, sum, o);

  if (tid == 0) {
    float lse = gm + logf(sum);
    double log_all = lgamma(21.0) + log(1767263190.0) + 19.0 * log(3.0);
    double res = log_all + (double)logf((float)cnt) - 2.0 * log(4096.0) + (double)lse;
    out[0] = (float)res;
    g_blocks_done = 0;                       // reset for next graph replay
    g_cnt = 0;
    g_gmax_u = 0u;
  }
}

// ---------------- Launch ------------------------------------------------------
extern "C" void kernel_launch(void* const* d_in, const int* in_sizes, int n_in,
                              void* d_out, int out_size) {
  const int*   ids = (const int*)d_in[0];
  const float* emb = (const float*)d_in[1];
  const float* lv  = (const float*)d_in[2];
  const float* fx  = (const float*)d_in[3];
  const float* Wf  = (const float*)d_in[4];
  const float* Wa  = (const float*)d_in[5];
  const float* bop = (const float*)d_in[6];
  float* out = (float*)d_out;

  // jax.random.key(42) -> (0,42); partitionable foldlike split
  uint32_t kop0, kop1, kg0, kg1;
  tf_block(0u, 42u, 0u, 0u, &kop0, &kop1);
  tf_block(0u, 42u, 0u, 1u, &kg0, &kg1);

  keygen_kernel<<<dim3(ROWN / 256, NSTEP + 1), 256>>>(kg0, kg1, kop0, kop1,
                                                      ids, emb, lv, fx, Wf, Wa, bop);
  scan_kernel<<<SCAN_BLK, SCAN_TPB>>>(out);
}